// round 9
// baseline (speedup 1.0000x reference)
#include <cuda_runtime.h>

// MedianPool2d 3x3, stride 1, reflect pad (1,1,1,1)
// float32 [16, 3, 512, 512] -> same shape.
//
// Persistent 8-row strips: each block (128 thr x 4 cols = 512 wide) walks 4
// iterations of 2 output rows. Rows roll between iterations (2 new vector
// loads per 2 output rows instead of 4) and the next iteration's loads are
// issued BEFORE the current iteration's compute so L2 latency is hidden
// inside each warp (fixes the correlated warp-start stall: issue was 67%).
// Vertical stage: packed f32x2 arithmetic compare-exchange (FMA pipe).
// Horizontal combine: scalar FMNMX (ALU pipe). Halos via warp shuffle with
// lane-0/31 predicated fixup loads; reflect folded into addresses.

#define W 512
#define H 512

typedef unsigned long long u64;
typedef unsigned int u32;

__device__ __forceinline__ u64 pk(float x, float y) {
    u64 r; asm("mov.b64 %0, {%1, %2};" : "=l"(r) : "f"(x), "f"(y)); return r;
}
__device__ __forceinline__ float2 upk(u64 v) {
    float2 f; asm("mov.b64 {%0, %1}, %2;" : "=f"(f.x), "=f"(f.y) : "l"(v)); return f;
}

// packed compare-exchange on 2 fp32 lanes: lo=min, hi=max
__device__ __forceinline__ void cex2(u64 a, u64 b, u64& lo, u64& hi) {
    const u64 n1 = 0xBF800000BF800000ULL;
    const u64 hf = 0x3F0000003F000000ULL;
    const u64 nh = 0xBF000000BF000000ULL;
    u64 s, d, k, h;
    asm("add.rn.f32x2 %0, %1, %2;" : "=l"(s) : "l"(a), "l"(b));
    asm("fma.rn.f32x2 %0, %1, %2, %3;" : "=l"(d) : "l"(b), "l"(n1), "l"(a)); // a-b
    k = d & 0x7FFFFFFF7FFFFFFFULL;                                           // |a-b|
    asm("mul.rn.f32x2 %0, %1, %2;" : "=l"(h) : "l"(s), "l"(hf));             // 0.5(a+b)
    asm("fma.rn.f32x2 %0, %1, %2, %3;" : "=l"(lo) : "l"(k), "l"(nh), "l"(h));
    asm("fma.rn.f32x2 %0, %1, %2, %3;" : "=l"(hi) : "l"(k), "l"(hf), "l"(h));
}

__device__ __forceinline__ float med3(float a, float b, float c) {
    return fmaxf(fminf(a, b), fminf(fmaxf(a, b), c));
}

struct Row3 { u64 a, b, c; };   // packed columns (1,2) (3,4) (0,5)

__device__ __forceinline__ void emit_row(const Row3& pl, const Row3& ph,
                                         const Row3& t,
                                         float* __restrict__ dst) {
    float4 res;
    u64 loa, mia, hia, loc, mic, hic, tm;
    cex2(pl.a, t.a, loa, tm);
    cex2(ph.a, tm, mia, hia);
    cex2(pl.c, t.c, loc, tm);
    cex2(ph.c, tm, mic, hic);

    float2 la = upk(loa), lc = upk(loc);
    float2 ma = upk(mia), mc = upk(mic);
    float2 ha = upk(hia), hc = upk(hic);

    float sA  = fmaxf(la.x, la.y);
    float tA  = fminf(ha.x, ha.y);
    float q0A = fminf(ma.x, ma.y), q1A = fmaxf(ma.x, ma.y);

    u64 lob, mib, hib;
    cex2(pl.b, t.b, lob, tm);
    cex2(ph.b, tm, mib, hib);
    float2 lb = upk(lob), mb = upk(mib), hb = upk(hib);

    res.x = med3(fmaxf(lc.x, sA),
                 fmaxf(q0A, fminf(q1A, mc.x)),
                 fminf(hc.x, tA));
    res.y = med3(fmaxf(sA, lb.x),
                 fmaxf(q0A, fminf(q1A, mb.x)),
                 fminf(tA, hb.x));

    float sB  = fmaxf(lb.x, lb.y);
    float tB  = fminf(hb.x, hb.y);
    float q0B = fminf(mb.x, mb.y), q1B = fmaxf(mb.x, mb.y);

    res.z = med3(fmaxf(la.y, sB),
                 fmaxf(q0B, fminf(q1B, ma.y)),
                 fminf(ha.y, tB));
    res.w = med3(fmaxf(sB, lc.y),
                 fmaxf(q0B, fminf(q1B, mc.y)),
                 fminf(tB, hc.y));

    *reinterpret_cast<float4*>(dst) = res;
}

__global__ __launch_bounds__(128, 8)
void median3x3_kernel(const float* __restrict__ x, float* __restrict__ out) {
    const int tid   = threadIdx.x;        // 0..127
    const int lane  = tid & 31;
    const int R     = blockIdx.x << 3;    // first output row of this 8-row strip
    const u32 plane = blockIdx.y;         // 0..47
    const int w0    = tid << 2;

    const u32 base = plane * (u32)(H * W);
    const u32 wlc = (w0 == 0)     ? 1u           : (u32)(w0 - 1);
    const u32 wrc = (w0 + 4 == W) ? (u32)(W - 2) : (u32)(w0 + 4);

    // raw row load: vector body + predicated lane-edge fixup loads
    auto LOAD = [&](int r, float4& q, float& lf, float& rf) {
        const int re = (r < 0) ? 1 : ((r >= H) ? H - 2 : r);
        const u32 o = base + (u32)re * W;
        q = *reinterpret_cast<const float4*>(x + o + w0);
        lf = 0.0f; rf = 0.0f;
        if (lane == 0)  lf = x[o + wlc];
        if (lane == 31) rf = x[o + wrc];
    };
    // finish: halo shuffle + select + pack
    auto PACK = [&](const float4& q, float lf, float rf) {
        float l = __shfl_up_sync(0xffffffffu, q.w, 1);
        float r = __shfl_down_sync(0xffffffffu, q.x, 1);
        l = (lane == 0)  ? lf : l;
        r = (lane == 31) ? rf : r;
        Row3 f;
        f.a = pk(q.x, q.y);
        f.b = pk(q.z, q.w);
        f.c = pk(l, r);
        return f;
    };

    // preload rows R-1 .. R+2 -> a,b,c,d
    float4 qa, qb, qc, qd;
    float lfa, rfa, lfb, rfb, lfc, rfc, lfd, rfd;
    LOAD(R - 1, qa, lfa, rfa);
    LOAD(R,     qb, lfb, rfb);
    LOAD(R + 1, qc, lfc, rfc);
    LOAD(R + 2, qd, lfd, rfd);
    Row3 a = PACK(qa, lfa, rfa);
    Row3 b = PACK(qb, lfb, rfb);
    Row3 c = PACK(qc, lfc, rfc);
    Row3 d = PACK(qd, lfd, rfd);

    float* od = out + base + (u32)R * W + w0;

#pragma unroll
    for (int k = 0; k < 4; k++) {
        // prefetch next iteration's 2 rows BEFORE compute (hidden by compute)
        float4 qe, qf; float lfe, rfe, lff, rff;
        if (k < 3) {
            LOAD(R + 2 * k + 3, qe, lfe, rfe);
            LOAD(R + 2 * k + 4, qf, lff, rff);
        }

        // pair = sort(b,c); outputs: row R+2k (third a), row R+2k+1 (third d)
        Row3 pl, ph;
        cex2(b.a, c.a, pl.a, ph.a);
        cex2(b.b, c.b, pl.b, ph.b);
        cex2(b.c, c.c, pl.c, ph.c);
        emit_row(pl, ph, a, od);
        emit_row(pl, ph, d, od + W);
        od += 2 * W;

        if (k < 3) {
            a = c; b = d;
            c = PACK(qe, lfe, rfe);
            d = PACK(qf, lff, rff);
        }
    }
}

extern "C" void kernel_launch(void* const* d_in, const int* in_sizes, int n_in,
                              void* d_out, int out_size) {
    const float* x = (const float*)d_in[0];
    float* out = (float*)d_out;
    dim3 grid(H / 8, 48);    // 64 strips x 48 planes = 3072 blocks
    dim3 block(128);
    median3x3_kernel<<<grid, block>>>(x, out);
}

// round 10
// speedup vs baseline: 1.0992x; 1.0992x over previous
#include <cuda_runtime.h>

// MedianPool2d 3x3, stride 1, reflect pad (1,1,1,1)
// float32 [16, 3, 512, 512] -> same shape.
//
// R10 = R7 (best: 18.8us kernel) + slot shaving:
//  - 4(W) x 2(H) outputs per thread, 40 regs, launch_bounds(128,12)
//  - vertical stage: packed f32x2 arithmetic compare-exchange (FMA pipe)
//  - horizontal combine: scalar FMNMX (ALU pipe)
//  - halos via warp shuffle; the lane-0 / lane-31 fixup loads are MERGED into
//    one predicated block (address select per lane) -> 4 fewer LDGs and one
//    fewer branch envelope than R7
//  - all 4 LDG.128 issued first, back-to-back

#define W 512
#define H 512

typedef unsigned long long u64;
typedef unsigned int u32;

__device__ __forceinline__ u64 pk(float x, float y) {
    u64 r; asm("mov.b64 %0, {%1, %2};" : "=l"(r) : "f"(x), "f"(y)); return r;
}
__device__ __forceinline__ float2 upk(u64 v) {
    float2 f; asm("mov.b64 {%0, %1}, %2;" : "=f"(f.x), "=f"(f.y) : "l"(v)); return f;
}

// packed compare-exchange on 2 fp32 lanes: lo=min, hi=max
__device__ __forceinline__ void cex2(u64 a, u64 b, u64& lo, u64& hi) {
    const u64 n1 = 0xBF800000BF800000ULL;
    const u64 hf = 0x3F0000003F000000ULL;
    const u64 nh = 0xBF000000BF000000ULL;
    u64 s, d, k, h;
    asm("add.rn.f32x2 %0, %1, %2;" : "=l"(s) : "l"(a), "l"(b));
    asm("fma.rn.f32x2 %0, %1, %2, %3;" : "=l"(d) : "l"(b), "l"(n1), "l"(a)); // a-b
    k = d & 0x7FFFFFFF7FFFFFFFULL;                                           // |a-b|
    asm("mul.rn.f32x2 %0, %1, %2;" : "=l"(h) : "l"(s), "l"(hf));             // 0.5(a+b)
    asm("fma.rn.f32x2 %0, %1, %2, %3;" : "=l"(lo) : "l"(k), "l"(nh), "l"(h));
    asm("fma.rn.f32x2 %0, %1, %2, %3;" : "=l"(hi) : "l"(k), "l"(hf), "l"(h));
}

__device__ __forceinline__ float med3(float a, float b, float c) {
    return fmaxf(fminf(a, b), fminf(fmaxf(a, b), c));
}

struct Row3 { u64 a, b, c; };   // packed columns (1,2) (3,4) (0,5)

__device__ __forceinline__ void emit_row(const Row3& pl, const Row3& ph,
                                         const Row3& t,
                                         float* __restrict__ dst) {
    float4 res;
    u64 loa, mia, hia, loc, mic, hic, tm;
    cex2(pl.a, t.a, loa, tm);
    cex2(ph.a, tm, mia, hia);
    cex2(pl.c, t.c, loc, tm);
    cex2(ph.c, tm, mic, hic);

    float2 la = upk(loa), lc = upk(loc);
    float2 ma = upk(mia), mc = upk(mic);
    float2 ha = upk(hia), hc = upk(hic);

    float sA  = fmaxf(la.x, la.y);
    float tA  = fminf(ha.x, ha.y);
    float q0A = fminf(ma.x, ma.y), q1A = fmaxf(ma.x, ma.y);

    u64 lob, mib, hib;
    cex2(pl.b, t.b, lob, tm);
    cex2(ph.b, tm, mib, hib);
    float2 lb = upk(lob), mb = upk(mib), hb = upk(hib);

    res.x = med3(fmaxf(lc.x, sA),
                 fmaxf(q0A, fminf(q1A, mc.x)),
                 fminf(hc.x, tA));
    res.y = med3(fmaxf(sA, lb.x),
                 fmaxf(q0A, fminf(q1A, mb.x)),
                 fminf(tA, hb.x));

    float sB  = fmaxf(lb.x, lb.y);
    float tB  = fminf(hb.x, hb.y);
    float q0B = fminf(mb.x, mb.y), q1B = fmaxf(mb.x, mb.y);

    res.z = med3(fmaxf(la.y, sB),
                 fmaxf(q0B, fminf(q1B, ma.y)),
                 fminf(ha.y, tB));
    res.w = med3(fmaxf(sB, lc.y),
                 fmaxf(q0B, fminf(q1B, mc.y)),
                 fminf(tB, hc.y));

    *reinterpret_cast<float4*>(dst) = res;
}

__global__ __launch_bounds__(128, 12)
void median3x3_kernel(const float* __restrict__ x, float* __restrict__ out) {
    const int tid   = threadIdx.x;        // 0..127
    const int lane  = tid & 31;
    const int h0    = blockIdx.x << 1;    // 2 output rows per block
    const u32 plane = blockIdx.y;         // 0..47
    const int w0    = tid << 2;

    const u32 base = plane * (u32)(H * W);

    // frame rows f0..f3 = input rows h0-1 .. h0+2 (reflected at edges)
    const int hr0 = (h0 == 0)     ? 1     : h0 - 1;
    const int hr3 = (h0 + 2 >= H) ? H - 2 : h0 + 2;

    const u32 o0 = base + (u32)hr0 * W;
    const u32 o1 = base + (u32)h0  * W;
    const u32 o2 = o1 + W;
    const u32 o3 = base + (u32)hr3 * W;

    // 4 vector loads, back-to-back, first
    float4 q0 = *reinterpret_cast<const float4*>(x + o0 + w0);
    float4 q1 = *reinterpret_cast<const float4*>(x + o1 + w0);
    float4 q2 = *reinterpret_cast<const float4*>(x + o2 + w0);
    float4 q3 = *reinterpret_cast<const float4*>(x + o3 + w0);

    // merged boundary fixup: lane 0 loads its left-halo column, lane 31 its
    // right-halo column (reflect folded into the address). One predicated
    // block, 4 loads total.
    float fx0, fx1, fx2, fx3;
    if ((lane == 0) | (lane == 31)) {
        const u32 col = (lane == 0)
            ? ((w0 == 0) ? 1u : (u32)(w0 - 1))
            : ((w0 + 4 == W) ? (u32)(W - 2) : (u32)(w0 + 4));
        fx0 = x[o0 + col];
        fx1 = x[o1 + col];
        fx2 = x[o2 + col];
        fx3 = x[o3 + col];
    }

    // halo exchange via shuffle; boundary lanes substitute their fixup value
    float l0 = __shfl_up_sync(0xffffffffu, q0.w, 1);
    float l1 = __shfl_up_sync(0xffffffffu, q1.w, 1);
    float l2 = __shfl_up_sync(0xffffffffu, q2.w, 1);
    float l3 = __shfl_up_sync(0xffffffffu, q3.w, 1);
    float e0 = __shfl_down_sync(0xffffffffu, q0.x, 1);
    float e1 = __shfl_down_sync(0xffffffffu, q1.x, 1);
    float e2 = __shfl_down_sync(0xffffffffu, q2.x, 1);
    float e3 = __shfl_down_sync(0xffffffffu, q3.x, 1);

    if (lane == 0)  { l0 = fx0; l1 = fx1; l2 = fx2; l3 = fx3; }
    if (lane == 31) { e0 = fx0; e1 = fx1; e2 = fx2; e3 = fx3; }

    Row3 f0, f1, f2, f3;
    f0.a = pk(q0.x, q0.y); f0.b = pk(q0.z, q0.w); f0.c = pk(l0, e0);
    f1.a = pk(q1.x, q1.y); f1.b = pk(q1.z, q1.w); f1.c = pk(l1, e1);
    f2.a = pk(q2.x, q2.y); f2.b = pk(q2.z, q2.w); f2.c = pk(l2, e2);
    f3.a = pk(q3.x, q3.y); f3.b = pk(q3.z, q3.w); f3.c = pk(l3, e3);

    // pair sort rows f1,f2 (both die afterward)
    Row3 pl, ph;
    cex2(f1.a, f2.a, pl.a, ph.a);
    cex2(f1.b, f2.b, pl.b, ph.b);
    cex2(f1.c, f2.c, pl.c, ph.c);

    float* o = out + o1 + w0;
    emit_row(pl, ph, f0, o);        // output row h0
    emit_row(pl, ph, f3, o + W);    // output row h0+1
}

extern "C" void kernel_launch(void* const* d_in, const int* in_sizes, int n_in,
                              void* d_out, int out_size) {
    const float* x = (const float*)d_in[0];
    float* out = (float*)d_out;
    dim3 grid(H / 2, 48);    // 256 row-pairs x 48 planes = 12288 blocks
    dim3 block(128);
    median3x3_kernel<<<grid, block>>>(x, out);
}